// round 3
// baseline (speedup 1.0000x reference)
#include <cuda_runtime.h>

#define NN 50000
#define NE 600000
#define H  128
#define HV4 32          // H/4
#define GG 16
#define OUTD 14
#define NL 3
#define GEN_EPS 1e-7f
#define BN_EPS  1e-5f
#define BN_BLOCKS 256
#define BN_CHUNK  196     // ceil(50000/256)
#define NBC 391           // ceil(NN/128)  (embed / scan blocks)
#define NBG 782           // ceil(NN/64)   (gemm blocks)
#define MAXPART 800

// ---------------- scratch (device globals; no allocation allowed) ------------
__device__ float g_hv [NN * H];
__device__ float g_x  [NN * H];
__device__ int   g_cnt[NN];
__device__ int   g_off[NN];
__device__ int   g_bsum[512];
__device__ int   g_boff[512];
__device__ int   g_edge[NE];                  // packed: src | (f0*3+f1)<<16
__device__ float g_part[2][MAXPART][H];
__device__ float g_scale[H];
__device__ float g_shift[H];
__device__ float g_etab[18 * H];
__device__ float g_hg[GG * H];
__device__ int   g_cntg[GG];

// ---------------- init -------------------------------------------------------
__global__ void k_zero() {
    int i = blockIdx.x * blockDim.x + threadIdx.x;
    if (i < NN)     g_cnt[i] = 0;
    if (i < GG * H) g_hg[i] = 0.f;
    if (i < GG)     g_cntg[i] = 0;
}

// node embedding + BN partial stats.  block = 128 nodes, thread = 1 channel.
__global__ void k_embed(const int* __restrict__ f0, const int* __restrict__ f1,
                        const float* __restrict__ W0, const float* __restrict__ W1) {
    __shared__ int sf0[128], sf1[128];
    int b = blockIdx.x, c = threadIdx.x;
    int n0 = b * 128;
    int cnt = min(128, NN - n0);
    if (c < cnt) { sf0[c] = f0[n0 + c]; sf1[c] = f1[n0 + c]; }
    __syncthreads();
    float s = 0.f, ss = 0.f;
    for (int i = 0; i < cnt; i++) {
        float v = W0[sf0[i] * H + c] + W1[sf1[i] * H + c];
        g_hv[(n0 + i) * H + c] = v;
        s += v; ss += v * v;
    }
    g_part[0][b][c] = s;
    g_part[1][b][c] = ss;
}

// ---------------- CSR build (dst-sorted), hierarchical scan ------------------
__global__ void k_count(const int* __restrict__ dst) {
    int e = blockIdx.x * blockDim.x + threadIdx.x;
    if (e < NE) atomicAdd(&g_cnt[dst[e]], 1);
}

__global__ void k_scan1() {
    __shared__ int wsum[4];
    int b = blockIdx.x, t = threadIdx.x;
    int idx = b * 128 + t;
    int v = (idx < NN) ? g_cnt[idx] : 0;
    int s = v;
    for (int d = 16; d > 0; d >>= 1) s += __shfl_down_sync(0xffffffffu, s, d);
    if ((t & 31) == 0) wsum[t >> 5] = s;
    __syncthreads();
    if (t == 0) g_bsum[b] = wsum[0] + wsum[1] + wsum[2] + wsum[3];
}

__global__ void k_scan2() {
    __shared__ int sm[512];
    int t = threadIdx.x;
    int v = (t < NBC) ? g_bsum[t] : 0;
    sm[t] = v;
    __syncthreads();
    for (int d = 1; d < 512; d <<= 1) {
        int u = (t >= d) ? sm[t - d] : 0;
        __syncthreads();
        sm[t] += u;
        __syncthreads();
    }
    if (t < NBC) g_boff[t] = sm[t] - v;
}

__global__ void k_scan3() {
    __shared__ int wsum[4];
    int b = blockIdx.x, t = threadIdx.x;
    int idx = b * 128 + t;
    int v = (idx < NN) ? g_cnt[idx] : 0;
    int inc = v;
    for (int d = 1; d < 32; d <<= 1) {
        int u = __shfl_up_sync(0xffffffffu, inc, d);
        if ((t & 31) >= d) inc += u;
    }
    if ((t & 31) == 31) wsum[t >> 5] = inc;
    __syncthreads();
    int w = t >> 5;
    int woff = 0;
    for (int i = 0; i < 4; i++) if (i < w) woff += wsum[i];
    if (idx < NN) g_off[idx] = g_boff[b] + woff + inc - v;
}

// scatter edges; g_off used as cursor (post: g_off[v] = segment END)
__global__ void k_scatter(const int* __restrict__ src, const int* __restrict__ dst,
                          const int* __restrict__ f0, const int* __restrict__ f1) {
    int e = blockIdx.x * blockDim.x + threadIdx.x;
    if (e >= NE) return;
    int d = dst[e];
    int j = atomicAdd(&g_off[d], 1);
    g_edge[j] = src[e] | ((f0[e] * 3 + f1[e]) << 16);
}

// ---------------- BN finalize + combined edge table --------------------------
__global__ void k_bnfin(const float* __restrict__ gamma, const float* __restrict__ bnb,
                        const float* __restrict__ ee0, const float* __restrict__ ee1,
                        int l, int nblk) {
    __shared__ float red[2][8][H];
    int tid = threadIdx.x;
    int c = tid & 127, g = tid >> 7;
    float s = 0.f, ss = 0.f;
    for (int b = g; b < nblk; b += 8) { s += g_part[0][b][c]; ss += g_part[1][b][c]; }
    red[0][g][c] = s; red[1][g][c] = ss;
    __syncthreads();
    if (tid < H) {
        float S = 0.f, SS = 0.f;
        for (int i = 0; i < 8; i++) { S += red[0][i][tid]; SS += red[1][i][tid]; }
        float mu  = S / (float)NN;
        float var = SS / (float)NN - mu * mu;
        float sc  = rsqrtf(var + BN_EPS) * gamma[l * H + tid];
        g_scale[tid] = sc;
        g_shift[tid] = bnb[l * H + tid] - mu * sc;
    }
    for (int i = tid; i < 18 * H; i += 1024) {
        int idx = i >> 7, cc = i & 127;
        int f0 = idx / 3, f1 = idx - f0 * 3;
        g_etab[i] = ee0[(l * 6 + f0) * H + cc] + ee1[(l * 3 + f1) * H + cc];
    }
}

// ---------------- GENConv aggregation: warp per dst node ---------------------
// BN-apply fused (hv1 = relu(hv*sc+sh)).  agg = sum(m*e)/sum(e),
// e = exp(m*beta) (no max-shift: m in (0,~10]).  x = hv1 + agg.
// 4-edge batches: all 8 gathers in flight before compute (MLP=8).
__global__ void __launch_bounds__(256) k_agg(const float* __restrict__ beta, int l) {
    __shared__ float etab[18 * H];
    int tid = threadIdx.x;
    for (int i = tid; i < 18 * H; i += 256) etab[i] = g_etab[i];
    __syncthreads();
    int gt   = blockIdx.x * 256 + tid;
    int wid  = gt >> 5;
    int lane = tid & 31;
    if (wid >= NN) return;
    float bl = beta[l];
    int end = g_off[wid];
    int beg = end - g_cnt[wid];
    const float4* __restrict__ hv4 = (const float4*)g_hv;
    const float4* __restrict__ et4 = (const float4*)etab;
    const int*    __restrict__ epk = g_edge;
    float4 sc = ((const float4*)g_scale)[lane];
    float4 sh = ((const float4*)g_shift)[lane];
    float4 num = make_float4(0.f, 0.f, 0.f, 0.f);
    float4 den = make_float4(0.f, 0.f, 0.f, 0.f);
#define EDGE_ELEM(hc, ec, scc, shc, nc, dc) do {                          \
        float t_ = fmaxf(fmaf(hc, scc, shc), 0.f);                        \
        float m_ = fmaxf(t_ + ec, 0.f) + GEN_EPS;                         \
        float x_ = __expf(m_ * bl);                                       \
        dc += x_; nc = fmaf(m_, x_, nc); } while (0)
#define EDGE_CMP(h_, e_) do {                                             \
        EDGE_ELEM(h_.x, e_.x, sc.x, sh.x, num.x, den.x);                  \
        EDGE_ELEM(h_.y, e_.y, sc.y, sh.y, num.y, den.y);                  \
        EDGE_ELEM(h_.z, e_.z, sc.z, sh.z, num.z, den.z);                  \
        EDGE_ELEM(h_.w, e_.w, sc.w, sh.w, num.w, den.w); } while (0)
    int j = beg;
    for (; j + 4 <= end; j += 4) {
        int pe[4];
#pragma unroll
        for (int u = 0; u < 4; u++) pe[u] = epk[j + u];
        float4 h[4], e[4];
#pragma unroll
        for (int u = 0; u < 4; u++) h[u] = hv4[(pe[u] & 0xFFFF) * HV4 + lane];
#pragma unroll
        for (int u = 0; u < 4; u++) e[u] = et4[(pe[u] >> 16) * HV4 + lane];
#pragma unroll
        for (int u = 0; u < 4; u++) EDGE_CMP(h[u], e[u]);
    }
    for (; j < end; j++) {
        int pe = epk[j];
        float4 h = hv4[(pe & 0xFFFF) * HV4 + lane];
        float4 e = et4[(pe >> 16) * HV4 + lane];
        EDGE_CMP(h, e);
    }
    float4 hr = hv4[wid * HV4 + lane];
    float4 xo;
    xo.x = fmaxf(fmaf(hr.x, sc.x, sh.x), 0.f);
    xo.y = fmaxf(fmaf(hr.y, sc.y, sh.y), 0.f);
    xo.z = fmaxf(fmaf(hr.z, sc.z, sh.z), 0.f);
    xo.w = fmaxf(fmaf(hr.w, sc.w, sh.w), 0.f);
    if (end > beg) {
        xo.x += num.x / den.x;
        xo.y += num.y / den.y;
        xo.z += num.z / den.z;
        xo.w += num.w / den.w;
    }
    ((float4*)g_x)[wid * HV4 + lane] = xo;
}

// ---------------- MLP GEMM: hv = x @ W + b + hv, + BN partial stats ----------
// Inner product on packed fp32x2 (FFMA2): 16 FFMA2/k-step instead of 32 FFMA.
__global__ void __launch_bounds__(256) k_gemm(const float* __restrict__ W,
                                              const float* __restrict__ bias) {
    __shared__ float Ws[32 * H];       // 16 KB, reused for stat reduction
    __shared__ float Xs[64 * 36];      // 9 KB (padded)
    int tid = threadIdx.x;
    int tx = tid & 15, ty = tid >> 4;
    int row0 = blockIdx.x * 64;
    unsigned long long acc[4][4];      // 4 rows x 4 f32x2 pairs (8 cols)
#pragma unroll
    for (int i = 0; i < 4; i++)
#pragma unroll
        for (int p = 0; p < 4; p++) acc[i][p] = 0ull;

    for (int kk = 0; kk < H; kk += 32) {
        const float4* Wg  = (const float4*)(W + kk * H);
        float4*       Ws4 = (float4*)Ws;
#pragma unroll
        for (int i = 0; i < 4; i++) Ws4[tid + i * 256] = Wg[tid + i * 256];
#pragma unroll
        for (int i = 0; i < 2; i++) {
            int f  = tid + i * 256;
            int r  = f >> 3, c4 = f & 7;
            int row = row0 + r;
            float4 v = make_float4(0.f, 0.f, 0.f, 0.f);
            if (row < NN) v = ((const float4*)(g_x + row * H + kk))[c4];
            ((float4*)(Xs + r * 36))[c4] = v;
        }
        __syncthreads();
#pragma unroll
        for (int k = 0; k < 32; k++) {
            unsigned long long ap[4];
#pragma unroll
            for (int i = 0; i < 4; i++) {
                unsigned int au = __float_as_uint(Xs[(ty * 4 + i) * 36 + k]);
                asm("mov.b64 %0, {%1, %1};" : "=l"(ap[i]) : "r"(au));
            }
            const ulonglong2* wp = (const ulonglong2*)&Ws[k * H + tx * 8];
            ulonglong2 bA = wp[0];      // pairs (b0,b1),(b2,b3)
            ulonglong2 bB = wp[1];      // pairs (b4,b5),(b6,b7)
#pragma unroll
            for (int i = 0; i < 4; i++) {
                asm("fma.rn.f32x2 %0, %1, %2, %0;" : "+l"(acc[i][0]) : "l"(ap[i]), "l"(bA.x));
                asm("fma.rn.f32x2 %0, %1, %2, %0;" : "+l"(acc[i][1]) : "l"(ap[i]), "l"(bA.y));
                asm("fma.rn.f32x2 %0, %1, %2, %0;" : "+l"(acc[i][2]) : "l"(ap[i]), "l"(bB.x));
                asm("fma.rn.f32x2 %0, %1, %2, %0;" : "+l"(acc[i][3]) : "l"(ap[i]), "l"(bB.y));
            }
        }
        __syncthreads();
    }
    // epilogue: out = acc + bias + hv_old; accumulate BN partial stats
    float4 br0 = ((const float4*)(bias + tx * 8))[0];
    float4 br1 = ((const float4*)(bias + tx * 8))[1];
    float br[8] = {br0.x, br0.y, br0.z, br0.w, br1.x, br1.y, br1.z, br1.w};
    float s_loc[8], ss_loc[8];
#pragma unroll
    for (int j = 0; j < 8; j++) { s_loc[j] = 0.f; ss_loc[j] = 0.f; }
#pragma unroll
    for (int i = 0; i < 4; i++) {
        int row = row0 + ty * 4 + i;
        if (row < NN) {
            float4* hr = (float4*)(g_hv + row * H + tx * 8);
            float4 h0 = hr[0], h1 = hr[1];
            float hold[8] = {h0.x, h0.y, h0.z, h0.w, h1.x, h1.y, h1.z, h1.w};
            float v[8];
#pragma unroll
            for (int p = 0; p < 4; p++) {
                uint2 u = *(uint2*)&acc[i][p];
                v[2 * p]     = __uint_as_float(u.x) + br[2 * p]     + hold[2 * p];
                v[2 * p + 1] = __uint_as_float(u.y) + br[2 * p + 1] + hold[2 * p + 1];
            }
            hr[0] = make_float4(v[0], v[1], v[2], v[3]);
            hr[1] = make_float4(v[4], v[5], v[6], v[7]);
#pragma unroll
            for (int j = 0; j < 8; j++) { s_loc[j] += v[j]; ss_loc[j] += v[j] * v[j]; }
        }
    }
    __syncthreads();
#pragma unroll
    for (int j = 0; j < 8; j++) {
        int ch = tx * 8 + j;
        Ws[ty * H + ch]        = s_loc[j];
        Ws[2048 + ty * H + ch] = ss_loc[j];
    }
    __syncthreads();
    if (tid < H) {
        float s = 0.f, ss = 0.f;
#pragma unroll
        for (int g = 0; g < 16; g++) { s += Ws[g * H + tid]; ss += Ws[2048 + g * H + tid]; }
        g_part[0][blockIdx.x][tid] = s;
        g_part[1][blockIdx.x][tid] = ss;
    }
}

// ---------------- graph pooling + output head --------------------------------
__global__ void k_pool(const int* __restrict__ gid) {
    int b = blockIdx.x, c = threadIdx.x;
    int n0 = b * BN_CHUNK;
    int n1 = min(NN, n0 + BN_CHUNK);
    if (n0 >= NN) return;
    float acc = 0.f;
    int curg = gid[n0];
    int run = 0;
    for (int n = n0; n < n1; n++) {
        int g = gid[n];
        if (g != curg) {
            atomicAdd(&g_hg[curg * H + c], acc);
            if (c == 0) atomicAdd(&g_cntg[curg], run);
            acc = 0.f; run = 0; curg = g;
        }
        acc += g_hv[n * H + c];
        run++;
    }
    atomicAdd(&g_hg[curg * H + c], acc);
    if (c == 0) atomicAdd(&g_cntg[curg], run);
}

__global__ void k_out(const float* __restrict__ Wo, const float* __restrict__ bo,
                      float* __restrict__ out) {
    int t = threadIdx.x;
    if (t >= GG * OUTD) return;
    int g = t / OUTD, o = t % OUTD;
    float inv = 1.f / (float)g_cntg[g];
    float acc = bo[o];
    for (int h = 0; h < H; h++) acc += g_hg[g * H + h] * inv * Wo[h * OUTD + o];
    out[t] = acc;
}

// ---------------- launch -----------------------------------------------------
extern "C" void kernel_launch(void* const* d_in, const int* in_sizes, int n_in,
                              void* d_out, int out_size) {
    const int* nf0  = (const int*)d_in[0];
    const int* nf1  = (const int*)d_in[1];
    const int* ef0  = (const int*)d_in[2];
    const int* ef1  = (const int*)d_in[3];
    const int* esrc = (const int*)d_in[4];
    const int* edst = (const int*)d_in[5];
    const int* gid  = (const int*)d_in[6];
    int base = (n_in > 7 && in_sizes[7] == 1) ? 8 : 7;
    const float* Wn0  = (const float*)d_in[base + 0];
    const float* Wn1  = (const float*)d_in[base + 1];
    const float* ee0  = (const float*)d_in[base + 2];
    const float* ee1  = (const float*)d_in[base + 3];
    const float* beta = (const float*)d_in[base + 4];
    const float* mlpW = (const float*)d_in[base + 5];
    const float* mlpb = (const float*)d_in[base + 6];
    const float* gam  = (const float*)d_in[base + 7];
    const float* bnb  = (const float*)d_in[base + 8];
    const float* Wo   = (const float*)d_in[base + 9];
    const float* bo   = (const float*)d_in[base + 10];
    float* out = (float*)d_out;

    k_zero<<<196, 256>>>();
    k_embed<<<NBC, 128>>>(nf0, nf1, Wn0, Wn1);
    k_count<<<(NE + 255) / 256, 256>>>(edst);
    k_scan1<<<NBC, 128>>>();
    k_scan2<<<1, 512>>>();
    k_scan3<<<NBC, 128>>>();
    k_scatter<<<(NE + 255) / 256, 256>>>(esrc, edst, ef0, ef1);

    for (int l = 0; l < NL; l++) {
        k_bnfin<<<1, 1024>>>(gam, bnb, ee0, ee1, l, l == 0 ? NBC : NBG);
        k_agg<<<(NN * 32 + 255) / 256, 256>>>(beta, l);
        k_gemm<<<NBG, 256>>>(mlpW + (size_t)l * H * H, mlpb + (size_t)l * H);
    }

    k_pool<<<BN_BLOCKS, H>>>(gid);
    k_out<<<1, 256>>>(Wo, bo, out);
}

// round 4
// speedup vs baseline: 1.2025x; 1.2025x over previous
#include <cuda_runtime.h>

#define NN 50000
#define NE 600000
#define H  128
#define HV4 32          // H/4
#define GG 16
#define OUTD 14
#define NL 3
#define GEN_EPS 1e-7f
#define BN_EPS  1e-5f
#define BN_BLOCKS 256
#define BN_CHUNK  196     // ceil(50000/256)
#define NBC 391           // ceil(NN/128)  (embed / scan / gemm blocks)
#define MAXPART 800

// ---------------- scratch (device globals; no allocation allowed) ------------
__device__ float g_hv [NN * H];
__device__ float g_x  [NN * H];
__device__ int   g_cnt[NN];
__device__ int   g_off[NN];
__device__ int   g_bsum[512];
__device__ int   g_boff[512];
__device__ int   g_edge[NE];                  // packed: src | (f0*3+f1)<<16
__device__ float g_part[2][MAXPART][H];
__device__ float g_scale[H];
__device__ float g_shift[H];
__device__ float g_etab[18 * H];
__device__ float g_hg[GG * H];
__device__ int   g_cntg[GG];

// node embedding + BN partial stats; also zeroes g_cnt for the CSR build.
__global__ void k_embed(const int* __restrict__ f0, const int* __restrict__ f1,
                        const float* __restrict__ W0, const float* __restrict__ W1) {
    __shared__ int sf0[128], sf1[128];
    int b = blockIdx.x, c = threadIdx.x;
    int n0 = b * 128;
    int cnt = min(128, NN - n0);
    if (c < cnt) {
        sf0[c] = f0[n0 + c]; sf1[c] = f1[n0 + c];
        g_cnt[n0 + c] = 0;
    }
    __syncthreads();
    float s = 0.f, ss = 0.f;
    for (int i = 0; i < cnt; i++) {
        float v = W0[sf0[i] * H + c] + W1[sf1[i] * H + c];
        g_hv[(n0 + i) * H + c] = v;
        s += v; ss += v * v;
    }
    g_part[0][b][c] = s;
    g_part[1][b][c] = ss;
}

// ---------------- CSR build (dst-sorted), hierarchical scan ------------------
__global__ void k_count(const int* __restrict__ dst) {
    int e = blockIdx.x * blockDim.x + threadIdx.x;
    if (e < NE) atomicAdd(&g_cnt[dst[e]], 1);
}

__global__ void k_scan1() {
    __shared__ int wsum[4];
    int b = blockIdx.x, t = threadIdx.x;
    int idx = b * 128 + t;
    int v = (idx < NN) ? g_cnt[idx] : 0;
    int s = v;
    for (int d = 16; d > 0; d >>= 1) s += __shfl_down_sync(0xffffffffu, s, d);
    if ((t & 31) == 0) wsum[t >> 5] = s;
    __syncthreads();
    if (t == 0) g_bsum[b] = wsum[0] + wsum[1] + wsum[2] + wsum[3];
}

__global__ void k_scan2() {   // also zeroes pool accumulators
    __shared__ int sm[512];
    int t = threadIdx.x;
    int v = (t < NBC) ? g_bsum[t] : 0;
    sm[t] = v;
    __syncthreads();
    for (int d = 1; d < 512; d <<= 1) {
        int u = (t >= d) ? sm[t - d] : 0;
        __syncthreads();
        sm[t] += u;
        __syncthreads();
    }
    if (t < NBC) g_boff[t] = sm[t] - v;
    for (int i = t; i < GG * H; i += 512) g_hg[i] = 0.f;
    if (t < GG) g_cntg[t] = 0;
}

__global__ void k_scan3() {
    __shared__ int wsum[4];
    int b = blockIdx.x, t = threadIdx.x;
    int idx = b * 128 + t;
    int v = (idx < NN) ? g_cnt[idx] : 0;
    int inc = v;
    for (int d = 1; d < 32; d <<= 1) {
        int u = __shfl_up_sync(0xffffffffu, inc, d);
        if ((t & 31) >= d) inc += u;
    }
    if ((t & 31) == 31) wsum[t >> 5] = inc;
    __syncthreads();
    int w = t >> 5;
    int woff = 0;
    for (int i = 0; i < 4; i++) if (i < w) woff += wsum[i];
    if (idx < NN) g_off[idx] = g_boff[b] + woff + inc - v;
}

// scatter edges; g_off used as cursor (post: g_off[v] = segment END)
__global__ void k_scatter(const int* __restrict__ src, const int* __restrict__ dst,
                          const int* __restrict__ f0, const int* __restrict__ f1) {
    int e = blockIdx.x * blockDim.x + threadIdx.x;
    if (e >= NE) return;
    int d = dst[e];
    int j = atomicAdd(&g_off[d], 1);
    g_edge[j] = src[e] | ((f0[e] * 3 + f1[e]) << 16);
}

// ---------------- BN finalize + combined edge table --------------------------
__global__ void k_bnfin(const float* __restrict__ gamma, const float* __restrict__ bnb,
                        const float* __restrict__ ee0, const float* __restrict__ ee1,
                        int l) {
    __shared__ float red[2][8][H];
    int tid = threadIdx.x;
    int c = tid & 127, g = tid >> 7;
    float s = 0.f, ss = 0.f;
    for (int b = g; b < NBC; b += 8) { s += g_part[0][b][c]; ss += g_part[1][b][c]; }
    red[0][g][c] = s; red[1][g][c] = ss;
    __syncthreads();
    if (tid < H) {
        float S = 0.f, SS = 0.f;
        for (int i = 0; i < 8; i++) { S += red[0][i][tid]; SS += red[1][i][tid]; }
        float mu  = S / (float)NN;
        float var = SS / (float)NN - mu * mu;
        float sc  = rsqrtf(var + BN_EPS) * gamma[l * H + tid];
        g_scale[tid] = sc;
        g_shift[tid] = bnb[l * H + tid] - mu * sc;
    }
    for (int i = tid; i < 18 * H; i += 1024) {
        int idx = i >> 7, cc = i & 127;
        int f0 = idx / 3, f1 = idx - f0 * 3;
        g_etab[i] = ee0[(l * 6 + f0) * H + cc] + ee1[(l * 3 + f1) * H + cc];
    }
}

// ---------------- GENConv aggregation: warp per dst node ---------------------
// BN-apply fused (hv1 = relu(hv*sc+sh)).  agg = sum(m*e)/sum(e),
// e = exp(m*beta) (no max-shift: m in (0,~10]).  x = hv1 + agg.
__global__ void __launch_bounds__(256) k_agg(const float* __restrict__ beta, int l) {
    __shared__ float etab[18 * H];
    int tid = threadIdx.x;
    for (int i = tid; i < 18 * H; i += 256) etab[i] = g_etab[i];
    __syncthreads();
    int gt   = blockIdx.x * 256 + tid;
    int wid  = gt >> 5;
    int lane = tid & 31;
    if (wid >= NN) return;
    float bl = beta[l];
    int end = g_off[wid];
    int beg = end - g_cnt[wid];
    const float4* __restrict__ hv4 = (const float4*)g_hv;
    const float4* __restrict__ et4 = (const float4*)etab;
    float4 sc = ((const float4*)g_scale)[lane];
    float4 sh = ((const float4*)g_shift)[lane];
    float4 num = make_float4(0.f, 0.f, 0.f, 0.f);
    float4 den = make_float4(0.f, 0.f, 0.f, 0.f);
#define EDGE_ELEM(hc, ec, scc, shc, nc, dc) do {                          \
        float t_ = fmaxf(fmaf(hc, scc, shc), 0.f);                        \
        float m_ = fmaxf(t_ + ec, 0.f) + GEN_EPS;                         \
        float x_ = __expf(m_ * bl);                                       \
        dc += x_; nc = fmaf(m_, x_, nc); } while (0)
#define EDGE_ONE(pe) do {                                                 \
        int src_ = (pe) & 0xFFFF;                                         \
        int idx_ = (pe) >> 16;                                            \
        float4 h_ = hv4[src_ * HV4 + lane];                               \
        float4 e_ = et4[idx_ * HV4 + lane];                               \
        EDGE_ELEM(h_.x, e_.x, sc.x, sh.x, num.x, den.x);                  \
        EDGE_ELEM(h_.y, e_.y, sc.y, sh.y, num.y, den.y);                  \
        EDGE_ELEM(h_.z, e_.z, sc.z, sh.z, num.z, den.z);                  \
        EDGE_ELEM(h_.w, e_.w, sc.w, sh.w, num.w, den.w); } while (0)
    int j = beg;
    for (; j + 2 <= end; j += 2) {
        int pe0 = g_edge[j], pe1 = g_edge[j + 1];
        EDGE_ONE(pe0);
        EDGE_ONE(pe1);
    }
    if (j < end) { int pe0 = g_edge[j]; EDGE_ONE(pe0); }
    float4 hr = hv4[wid * HV4 + lane];
    float4 xo;
    xo.x = fmaxf(fmaf(hr.x, sc.x, sh.x), 0.f);
    xo.y = fmaxf(fmaf(hr.y, sc.y, sh.y), 0.f);
    xo.z = fmaxf(fmaf(hr.z, sc.z, sh.z), 0.f);
    xo.w = fmaxf(fmaf(hr.w, sc.w, sh.w), 0.f);
    if (end > beg) {
        xo.x += num.x / den.x;
        xo.y += num.y / den.y;
        xo.z += num.z / den.z;
        xo.w += num.w / den.w;
    }
    ((float4*)g_x)[wid * HV4 + lane] = xo;
}

// ---------------- MLP GEMM: hv = x @ W + b + hv, + BN partial stats ----------
// 128-row x 128-col tile, 256 threads, 8x8 register blocking.
// X staged TRANSPOSED in smem so the a-operand is 2x LDS.128 broadcast.
__global__ void __launch_bounds__(256) k_gemm(const float* __restrict__ W,
                                              const float* __restrict__ bias) {
    __shared__ float Ws[32 * H];        // 16 KB; reused for stat reduction
    __shared__ float XsT[32 * 132];     // 16.5 KB transposed (k-major), pad 132
    int tid = threadIdx.x;
    int tx = tid & 15, ty = tid >> 4;
    int row0 = blockIdx.x * 128;
    float acc[8][8];
#pragma unroll
    for (int i = 0; i < 8; i++)
#pragma unroll
        for (int j = 0; j < 8; j++) acc[i][j] = 0.f;

    for (int kk = 0; kk < H; kk += 32) {
        const float4* Wg  = (const float4*)(W + kk * H);
        float4*       Ws4 = (float4*)Ws;
#pragma unroll
        for (int i = 0; i < 4; i++) Ws4[tid + i * 256] = Wg[tid + i * 256];
#pragma unroll
        for (int i = 0; i < 4; i++) {
            int f  = tid + i * 256;              // 0..1023
            int r  = f >> 3, c4 = f & 7;         // r: row in tile, c4: float4 within k-chunk
            int row = row0 + r;
            float4 v = make_float4(0.f, 0.f, 0.f, 0.f);
            if (row < NN) v = ((const float4*)(g_x + row * H + kk))[c4];
            XsT[(c4 * 4 + 0) * 132 + r] = v.x;
            XsT[(c4 * 4 + 1) * 132 + r] = v.y;
            XsT[(c4 * 4 + 2) * 132 + r] = v.z;
            XsT[(c4 * 4 + 3) * 132 + r] = v.w;
        }
        __syncthreads();
#pragma unroll
        for (int k = 0; k < 32; k++) {
            float4 a0 = *(const float4*)&XsT[k * 132 + ty * 8];
            float4 a1 = *(const float4*)&XsT[k * 132 + ty * 8 + 4];
            float4 b0 = *(const float4*)&Ws[k * H + tx * 8];
            float4 b1 = *(const float4*)&Ws[k * H + tx * 8 + 4];
            float a[8] = {a0.x, a0.y, a0.z, a0.w, a1.x, a1.y, a1.z, a1.w};
            float b[8] = {b0.x, b0.y, b0.z, b0.w, b1.x, b1.y, b1.z, b1.w};
#pragma unroll
            for (int i = 0; i < 8; i++)
#pragma unroll
                for (int j = 0; j < 8; j++) acc[i][j] += a[i] * b[j];
        }
        __syncthreads();
    }
    // epilogue: out = acc + bias + hv_old; accumulate BN partial stats
    float4 br0 = ((const float4*)(bias + tx * 8))[0];
    float4 br1 = ((const float4*)(bias + tx * 8))[1];
    float br[8] = {br0.x, br0.y, br0.z, br0.w, br1.x, br1.y, br1.z, br1.w};
    float s_loc[8], ss_loc[8];
#pragma unroll
    for (int j = 0; j < 8; j++) { s_loc[j] = 0.f; ss_loc[j] = 0.f; }
#pragma unroll
    for (int i = 0; i < 8; i++) {
        int row = row0 + ty * 8 + i;
        if (row < NN) {
            float4* hr = (float4*)(g_hv + row * H + tx * 8);
            float4 h0 = hr[0], h1 = hr[1];
            float hold[8] = {h0.x, h0.y, h0.z, h0.w, h1.x, h1.y, h1.z, h1.w};
            float v[8];
#pragma unroll
            for (int j = 0; j < 8; j++) v[j] = acc[i][j] + br[j] + hold[j];
            hr[0] = make_float4(v[0], v[1], v[2], v[3]);
            hr[1] = make_float4(v[4], v[5], v[6], v[7]);
#pragma unroll
            for (int j = 0; j < 8; j++) { s_loc[j] += v[j]; ss_loc[j] += v[j] * v[j]; }
        }
    }
    __syncthreads();
#pragma unroll
    for (int j = 0; j < 8; j++) {
        int ch = tx * 8 + j;
        Ws[ty * H + ch]        = s_loc[j];
        Ws[2048 + ty * H + ch] = ss_loc[j];
    }
    __syncthreads();
    if (tid < H) {
        float s = 0.f, ss = 0.f;
#pragma unroll
        for (int g = 0; g < 16; g++) { s += Ws[g * H + tid]; ss += Ws[2048 + g * H + tid]; }
        g_part[0][blockIdx.x][tid] = s;
        g_part[1][blockIdx.x][tid] = ss;
    }
}

// ---------------- graph pooling + output head --------------------------------
__global__ void k_pool(const int* __restrict__ gid) {
    int b = blockIdx.x, c = threadIdx.x;
    int n0 = b * BN_CHUNK;
    int n1 = min(NN, n0 + BN_CHUNK);
    if (n0 >= NN) return;
    float acc = 0.f;
    int curg = gid[n0];
    int run = 0;
    for (int n = n0; n < n1; n++) {
        int g = gid[n];
        if (g != curg) {
            atomicAdd(&g_hg[curg * H + c], acc);
            if (c == 0) atomicAdd(&g_cntg[curg], run);
            acc = 0.f; run = 0; curg = g;
        }
        acc += g_hv[n * H + c];
        run++;
    }
    atomicAdd(&g_hg[curg * H + c], acc);
    if (c == 0) atomicAdd(&g_cntg[curg], run);
}

__global__ void k_out(const float* __restrict__ Wo, const float* __restrict__ bo,
                      float* __restrict__ out) {
    int t = threadIdx.x;
    if (t >= GG * OUTD) return;
    int g = t / OUTD, o = t % OUTD;
    float inv = 1.f / (float)g_cntg[g];
    float acc = bo[o];
    for (int h = 0; h < H; h++) acc += g_hg[g * H + h] * inv * Wo[h * OUTD + o];
    out[t] = acc;
}

// ---------------- launch -----------------------------------------------------
extern "C" void kernel_launch(void* const* d_in, const int* in_sizes, int n_in,
                              void* d_out, int out_size) {
    const int* nf0  = (const int*)d_in[0];
    const int* nf1  = (const int*)d_in[1];
    const int* ef0  = (const int*)d_in[2];
    const int* ef1  = (const int*)d_in[3];
    const int* esrc = (const int*)d_in[4];
    const int* edst = (const int*)d_in[5];
    const int* gid  = (const int*)d_in[6];
    int base = (n_in > 7 && in_sizes[7] == 1) ? 8 : 7;
    const float* Wn0  = (const float*)d_in[base + 0];
    const float* Wn1  = (const float*)d_in[base + 1];
    const float* ee0  = (const float*)d_in[base + 2];
    const float* ee1  = (const float*)d_in[base + 3];
    const float* beta = (const float*)d_in[base + 4];
    const float* mlpW = (const float*)d_in[base + 5];
    const float* mlpb = (const float*)d_in[base + 6];
    const float* gam  = (const float*)d_in[base + 7];
    const float* bnb  = (const float*)d_in[base + 8];
    const float* Wo   = (const float*)d_in[base + 9];
    const float* bo   = (const float*)d_in[base + 10];
    float* out = (float*)d_out;

    k_embed<<<NBC, 128>>>(nf0, nf1, Wn0, Wn1);
    k_count<<<(NE + 255) / 256, 256>>>(edst);
    k_scan1<<<NBC, 128>>>();
    k_scan2<<<1, 512>>>();
    k_scan3<<<NBC, 128>>>();
    k_scatter<<<(NE + 255) / 256, 256>>>(esrc, edst, ef0, ef1);

    for (int l = 0; l < NL; l++) {
        k_bnfin<<<1, 1024>>>(gam, bnb, ee0, ee1, l);
        k_agg<<<(NN * 32 + 255) / 256, 256>>>(beta, l);
        k_gemm<<<NBC, 256>>>(mlpW + (size_t)l * H * H, mlpb + (size_t)l * H);
    }

    k_pool<<<BN_BLOCKS, H>>>(gid);
    k_out<<<1, 256>>>(Wo, bo, out);
}